// round 14
// baseline (speedup 1.0000x reference)
#include <cuda_runtime.h>
#include <cuda_bf16.h>

// SmoothRankAP (1 - mAP, sigmoid rank approx), B=512, tau=0.01.
//
// Math: sigmoid((sj-si)/tau) = 0.5 + 0.5*tanh((sj-si)/(2*tau)); tanh(0)=0
// exactly, so including the diagonal in both sums gives (after x2 cancel):
//   term = (npos + 1 + sum_pos tanh) / (513 + sum_all tanh)
// Only positive (b,i) pairs contribute (sim_pos==0 otherwise): O(B*npos*B).
//
// Layout: one row b per WARP PAIR; the whole row lives in 16 regs/lane
// (j = k*32 + lane), target row as 16 warp-uniform ballot words. Warp parity
// alternates positives so one warp's MUFU work hides the other's shuffle-
// reduce chain. No smem in the hot loop. Fused final reduction via arrival
// counter (deterministic fixed-order sums; counter reset for graph replay).

#define BSZ      512
#define NTHREADS 256          // 8 warps: 4 rows/block, 2 warps/row
#define GRID     (BSZ / 4)    // 128 blocks
#define SCALE    50.0f        // 1/(2*tau)

__device__ float g_ap[BSZ];
__device__ unsigned int g_arrive = 0;

__device__ __forceinline__ float tanh_approx(float x) {
    float y; asm("tanh.approx.f32 %0, %1;" : "=f"(y) : "f"(x)); return y;
}

__global__ void __launch_bounds__(NTHREADS)
smoothap_kernel(const float* __restrict__ scores,
                const float* __restrict__ target,
                float* __restrict__ out) {
    const int tid    = threadIdx.x;
    const int lane   = tid & 31;
    const int wid    = tid >> 5;        // 0..7
    const int rowsub = wid >> 1;        // 0..3: which row of this block
    const int parity = wid & 1;         // which half of the positives
    const int b      = blockIdx.x * 4 + rowsub;

    __shared__ float sm_acc[8];
    __shared__ int   s_is_last;

    // ---- load row b into registers (j = k*32 + lane), build target bits ----
    float    s[16];
    float    tmask[16];
    unsigned mw[16];                    // warp-uniform ballot words
    int npos = 0;
    const float* __restrict__ srow = scores + b * BSZ;
    const float* __restrict__ trow = target + b * BSZ;
    #pragma unroll
    for (int k = 0; k < 16; k++) {
        s[k] = srow[k * 32 + lane] * SCALE;
        const float tv = trow[k * 32 + lane];
        const unsigned m = __ballot_sync(0xffffffffu, tv > 0.5f);
        mw[k] = m;
        tmask[k] = ((m >> lane) & 1u) ? 1.0f : 0.0f;
        npos += __popc(m);
    }

    // ---- iterate positives of this row; this warp takes every other one ----
    float ap_acc = 0.0f;
    int cnt = 0;
    const float cnum = (float)npos + 1.0f;
    #pragma unroll
    for (int kb = 0; kb < 16; kb++) {
        unsigned m = mw[kb];
        while (m) {                     // warp-uniform loop
            const int src = __ffs(m) - 1;
            m &= m - 1u;
            if ((cnt++ & 1) == parity) {
                const float si = __shfl_sync(0xffffffffu, s[kb], src);
                float sa = 0.0f, sp = 0.0f;
                #pragma unroll
                for (int kk = 0; kk < 16; kk++) {
                    const float th = tanh_approx(s[kk] - si);
                    sa += th;
                    sp = fmaf(tmask[kk], th, sp);
                }
                #pragma unroll
                for (int o = 16; o; o >>= 1) {
                    sa += __shfl_xor_sync(0xffffffffu, sa, o);
                    sp += __shfl_xor_sync(0xffffffffu, sp, o);
                }
                ap_acc += __fdividef(cnum + sp, 513.0f + sa);
            }
        }
    }

    // ---- combine warp pair, write ap[b] ----
    if (lane == 0) sm_acc[wid] = ap_acc;
    __syncthreads();
    if (parity == 0 && lane == 0)
        g_ap[b] = (sm_acc[wid] + sm_acc[wid + 1]) / (float)npos;

    // ---- fused final reduction (last-arriving block) ----
    if (tid == 0) {
        __threadfence();                               // release g_ap writes
        const unsigned old = atomicAdd(&g_arrive, 1u);
        s_is_last = (old == (unsigned)(GRID - 1));
        if (s_is_last) __threadfence();                // acquire all g_ap
    }
    __syncthreads();

    if (s_is_last) {
        float v = g_ap[tid] + g_ap[tid + NTHREADS];    // fixed order
        #pragma unroll
        for (int o = 16; o; o >>= 1)
            v += __shfl_xor_sync(0xffffffffu, v, o);
        __syncthreads();                               // sm_acc reuse
        if (lane == 0) sm_acc[wid] = v;
        __syncthreads();
        if (tid == 0) {
            float tot = 0.0f;
            #pragma unroll
            for (int w = 0; w < 8; w++) tot += sm_acc[w];
            out[0] = 1.0f - tot * (1.0f / (float)BSZ);
            g_arrive = 0;                              // reset for graph replay
        }
    }
}

extern "C" void kernel_launch(void* const* d_in, const int* in_sizes, int n_in,
                              void* d_out, int out_size) {
    const float* scores = (const float*)d_in[0];
    const float* target = (const float*)d_in[1];
    float* out = (float*)d_out;
    smoothap_kernel<<<GRID, NTHREADS>>>(scores, target, out);
}

// round 15
// speedup vs baseline: 1.6000x; 1.6000x over previous
#include <cuda_runtime.h>
#include <cuda_bf16.h>

// SmoothRankAP (1 - mAP, sigmoid rank approx), B=512, tau=0.01.
//
// term(b,i) = (npos + 1 + sum_j t[j]*tanh(50*(s[j]-s[i]))) /
//             (513      + sum_j      tanh(50*(s[j]-s[i])))     [i positive]
// (sigmoid = 0.5+0.5*tanh(x/2); tanh(0)=0 keeps the diagonal algebra exact;
//  the factor 2 cancels in the ratio. Validated rel_err=0.0 in round 14.)
//
// LANE-TRANSPOSED layout (fixes R14's occupancy collapse): lanes = positives,
// loop = j. One row per 256-thread block; warp w handles j in [w*64,(w+1)*64);
// lane l accumulates (sa,sp) for positive l. No per-positive shuffle reduces
// (R3 paid 10 SHFLs x 8192 positives; here: 5 SHFLs x 512 rows). Inner loop
// has no serial chain beyond a 4-cyc accumulator -> MUFU-throughput bound.
// grid=512 -> 3-4 blocks/SM, ~24-32 warps/SM. Fused tail via arrival counter.

#define BSZ      512
#define NTHREADS 256
#define SCALE    50.0f        // 1/(2*tau)

__device__ float g_ap[BSZ];
__device__ unsigned int g_arrive = 0;

__device__ __forceinline__ float tanh_approx(float x) {
    float y; asm("tanh.approx.f32 %0, %1;" : "=f"(y) : "f"(x)); return y;
}

__global__ void __launch_bounds__(NTHREADS)
smoothap_kernel(const float* __restrict__ scores,
                const float* __restrict__ target,
                float* __restrict__ out) {
    const int b    = blockIdx.x;
    const int tid  = threadIdx.x;
    const int lane = tid & 31;
    const int wid  = tid >> 5;          // 0..7

    __shared__ float    s_sc[BSZ];      // scores*SCALE for row b
    __shared__ unsigned t_words[16];    // target row bitmask (16 x 32 j's)
    __shared__ short    pos_idx[BSZ];   // compacted positive indices
    __shared__ float    sa_part[8][32]; // per-warp partials, [warp][lane=pos]
    __shared__ float    sp_part[8][32];
    __shared__ float    sm8[8];
    __shared__ int      s_is_last;

    // ---- load row b (2 elements/thread, coalesced); build bitmask ----
    const float tv0 = target[b * BSZ + tid];
    const float tv1 = target[b * BSZ + NTHREADS + tid];
    s_sc[tid]            = scores[b * BSZ + tid] * SCALE;
    s_sc[tid + NTHREADS] = scores[b * BSZ + NTHREADS + tid] * SCALE;
    const unsigned m0 = __ballot_sync(0xffffffffu, tv0 > 0.5f);  // word wid
    const unsigned m1 = __ballot_sync(0xffffffffu, tv1 > 0.5f);  // word wid+8
    if (lane == 0) { t_words[wid] = m0; t_words[wid + 8] = m1; }
    __syncthreads();

    // ---- deterministic compaction of positive indices ----
    int npos = 0, base0 = 0, base1 = 0;
    #pragma unroll
    for (int w = 0; w < 16; w++) {
        const int c = __popc(t_words[w]);
        if (w == wid)     base0 = npos;
        if (w == wid + 8) base1 = npos;
        npos += c;
    }
    if (tv0 > 0.5f)
        pos_idx[base0 + __popc(m0 & ((1u << lane) - 1u))] = (short)tid;
    if (tv1 > 0.5f)
        pos_idx[base1 + __popc(m1 & ((1u << lane) - 1u))] = (short)(NTHREADS + tid);
    __syncthreads();

    // ---- main loop: lanes = positives (chunks of 32), warps = j-chunks ----
    const int jbase = wid * 64;
    const unsigned bw0 = t_words[2 * wid];       // warp-uniform mask words
    const unsigned bw1 = t_words[2 * wid + 1];
    const float cnum = (float)npos + 1.0f;
    float row_ap = 0.0f;                          // meaningful in warp 0

    for (int p0 = 0; p0 < npos; p0 += 32) {       // usually 1 iteration
        const int  myp    = p0 + lane;
        const bool active = (myp < npos);
        const float si = s_sc[pos_idx[active ? myp : 0]];

        float sa = 0.0f, sp = 0.0f;
        #pragma unroll
        for (int u = 0; u < 32; u++) {
            const float th = tanh_approx(s_sc[jbase + u] - si);
            sa += th;
            if (bw0 & (1u << u)) sp += th;        // uniform select, no branch
        }
        #pragma unroll
        for (int u = 0; u < 32; u++) {
            const float th = tanh_approx(s_sc[jbase + 32 + u] - si);
            sa += th;
            if (bw1 & (1u << u)) sp += th;
        }
        sa_part[wid][lane] = sa;
        sp_part[wid][lane] = sp;
        __syncthreads();

        if (wid == 0) {                           // combine 8 warps, fixed order
            float SA = 0.0f, SP = 0.0f;
            #pragma unroll
            for (int w = 0; w < 8; w++) { SA += sa_part[w][lane]; SP += sp_part[w][lane]; }
            float term = active ? __fdividef(cnum + SP, 513.0f + SA) : 0.0f;
            #pragma unroll
            for (int o = 16; o; o >>= 1)
                term += __shfl_xor_sync(0xffffffffu, term, o);
            if (lane == 0) row_ap += term;
        }
        __syncthreads();                          // partials reusable next chunk
    }

    if (tid == 0) g_ap[b] = row_ap / (float)npos;

    // ---- fused final reduction (last-arriving block) ----
    if (tid == 0) {
        __threadfence();                           // release g_ap[b]
        const unsigned old = atomicAdd(&g_arrive, 1u);
        s_is_last = (old == (unsigned)(BSZ - 1));
        if (s_is_last) __threadfence();            // acquire all g_ap
    }
    __syncthreads();

    if (s_is_last) {
        float v = g_ap[tid] + g_ap[tid + NTHREADS];   // fixed order
        #pragma unroll
        for (int o = 16; o; o >>= 1)
            v += __shfl_xor_sync(0xffffffffu, v, o);
        if (lane == 0) sm8[wid] = v;
        __syncthreads();
        if (tid == 0) {
            float tot = 0.0f;
            #pragma unroll
            for (int w = 0; w < 8; w++) tot += sm8[w];
            out[0] = 1.0f - tot * (1.0f / (float)BSZ);
            g_arrive = 0;                             // reset for graph replay
        }
    }
}

extern "C" void kernel_launch(void* const* d_in, const int* in_sizes, int n_in,
                              void* d_out, int out_size) {
    const float* scores = (const float*)d_in[0];
    const float* target = (const float*)d_in[1];
    float* out = (float*)d_out;
    smoothap_kernel<<<BSZ, NTHREADS>>>(scores, target, out);
}